// round 15
// baseline (speedup 1.0000x reference)
#include <cuda_runtime.h>
#include <cstdint>

#define BATCH 16
#define NA    25200
#define NC    80
#define TOPK  2048
#define NMS_T 0.45f
#define CONF_T 0.25f
#define FULLM 0xffffffffu

// ---------------- scratch (__device__ globals; zero-initialized at load) ----------------
__device__ float              g_scores[BATCH * NA];          // conf-filtered max score
__device__ int                g_labels[BATCH * NA];          // argmax class
__device__ unsigned           g_hist[BATCH * 8192];          // per-image top-13-bit histogram
__device__ float              g_topboxes[BATCH * TOPK * 4];  // gathered boxes (xyxy)
__device__ float              g_topscore[BATCH * TOPK];
__device__ int                g_topidx[BATCH * TOPK];
__device__ __align__(16) unsigned long long g_mask[(size_t)BATCH * TOPK * 32]; // 8MB bit-matrix

// ---------------- K1: score/argmax, smem-staged coalesced + histogram ----------------
__global__ void __launch_bounds__(128) k_scores(const float* __restrict__ obj,
                                                const float* __restrict__ cls) {
    __shared__ float sh[128 * 81];                 // 81-stride: conflict-free reduce
    const int t = threadIdx.x;
    const int a0 = blockIdx.x * 128;               // first flattened anchor of block
    const float4* __restrict__ src = reinterpret_cast<const float4*>(cls) + (size_t)a0 * 20;

#pragma unroll
    for (int k = 0; k < 20; ++k) {                 // perfectly coalesced gmem loads
        int fi = k * 128 + t;
        float4 v = src[fi];
        int a = fi / 20, c = (fi % 20) * 4;
        float* row = sh + a * 81 + c;
        row[0] = v.x; row[1] = v.y; row[2] = v.z; row[3] = v.w;
    }
    __syncthreads();

    const int g = a0 + t;
    const float o = obj[g];
    const float* row = sh + t * 81;
    float best = -1.0f; int bi = 0;
#pragma unroll
    for (int c = 0; c < NC; ++c) {                 // strict > : first-index argmax
        float p = o * row[c];
        if (p > best) { best = p; bi = c; }
    }
    float s = (best > CONF_T) ? best : 0.0f;
    g_scores[g] = s;
    g_labels[g] = bi;

    // per-image histogram of top 13 bits of the filtered score (== key>>34)
    const int img = g / NA;
    const unsigned bin = __float_as_uint(s) >> 19;          // < 8192
    unsigned key = ((unsigned)img << 13) | bin;
    unsigned mm = __match_any_sync(FULLM, key);             // warp-aggregate same-bin
    if ((t & 31) == (__ffs(mm) - 1))
        atomicAdd(&g_hist[img * 8192 + bin], (unsigned)__popc(mm));
}

// ---------------- K2: exact top-2048 (sorted desc, tie -> low idx) ----------------
// composite key: (float_bits(score) << 15) | (32767 - idx) -- distinct, order == top_k.
// One full scan: winners (bin > d1) front, boundary candidates (bin == d1) back of a
// zero-padded 4096 buffer; bitonic sort 4096 desc; first 2048 = exact sorted top-K.
__global__ void k_topk(const float* __restrict__ boxes) {
    extern __shared__ __align__(16) unsigned char dsm[];
    unsigned long long* keys = reinterpret_cast<unsigned long long*>(dsm);     // 4096 (32KB)
    unsigned* hist = reinterpret_cast<unsigned*>(dsm + 32768);                 // 8192 (32KB)
    __shared__ unsigned sums256[32];
    __shared__ unsigned sh_cw, sh_cc;
    __shared__ int sh_d1;

    const int b = blockIdx.x, t = threadIdx.x;          // 1024 threads
    const float* __restrict__ sc = g_scores + (size_t)b * NA;
    unsigned* __restrict__ gh = g_hist + b * 8192;

    if (t == 0) { sh_cw = 0u; sh_cc = 0u; }
    for (int i = t; i < 8192; i += 1024) hist[i] = gh[i];
    for (int i = t; i < 4096; i += 1024) keys[i] = 0ull;
    __syncthreads();
    for (int i = t; i < 8192; i += 1024) gh[i] = 0u;    // reset for next graph replay

    // region sums: warp w owns bins [w*256, w*256+256)
    {
        unsigned s8 = 0;
#pragma unroll
        for (int i = 0; i < 8; ++i) s8 += hist[t * 8 + i];
#pragma unroll
        for (int o = 16; o > 0; o >>= 1) s8 += __shfl_down_sync(FULLM, s8, o);
        if ((t & 31) == 0) sums256[t >> 5] = s8;
    }
    __syncthreads();

    if (t < 32) {                                        // warp 0: suffix-select d1
        const int lane = t;
        unsigned c1 = sums256[lane];
        unsigned v = c1;
#pragma unroll
        for (int o = 1; o < 32; o <<= 1) {
            unsigned u = __shfl_down_sync(FULLM, v, o);
            if (lane + o < 32) v += u;
        }
        unsigned sufex = v - c1;
        unsigned bal = __ballot_sync(FULLM, (sufex < TOPK) && (TOPK <= v));
        int L1 = __ffs(bal) - 1;
        unsigned rem = TOPK - __shfl_sync(FULLM, sufex, L1);

        int b2 = L1 * 256 + lane * 8;
        unsigned c2 = 0;
#pragma unroll
        for (int i = 0; i < 8; ++i) c2 += hist[b2 + i];
        v = c2;
#pragma unroll
        for (int o = 1; o < 32; o <<= 1) {
            unsigned u = __shfl_down_sync(FULLM, v, o);
            if (lane + o < 32) v += u;
        }
        sufex = v - c2;
        bal = __ballot_sync(FULLM, (sufex < rem) && (rem <= v));
        int L2 = __ffs(bal) - 1;
        rem -= __shfl_sync(FULLM, sufex, L2);
        if (lane == L2) {
            int b3 = L1 * 256 + L2 * 8;
            unsigned cum = 0; int d = 7;
            for (d = 7; d >= 0; --d) {
                unsigned h = hist[b3 + d];
                if (cum + h >= rem) break;
                cum += h;
            }
            sh_d1 = b3 + d;
        }
    }
    __syncthreads();
    const unsigned d1 = (unsigned)sh_d1;

    // single full scan: scatter winners / boundary candidates
    for (int n = t; n < NA; n += 1024) {
        unsigned bits = __float_as_uint(sc[n]);
        unsigned bin = bits >> 19;
        if (bin >= d1) {
            unsigned long long key =
                ((unsigned long long)bits << 15) | (unsigned long long)(32767 - n);
            if (bin > d1) { unsigned p = atomicAdd(&sh_cw, 1u); keys[p] = key; }
            else          { unsigned p = atomicAdd(&sh_cc, 1u); keys[4095u - p] = key; }
        }
    }
    __syncthreads();

    // bitonic sort 4096 descending
    for (int kk = 2; kk <= 4096; kk <<= 1) {
        for (int j = kk >> 1; j > 0; j >>= 1) {
            for (int i = t; i < 4096; i += 1024) {
                int l = i ^ j;
                if (l > i) {
                    bool dir = ((i & kk) == 0);
                    unsigned long long a = keys[i], c = keys[l];
                    if ((a < c) == dir) { keys[i] = c; keys[l] = a; }
                }
            }
            __syncthreads();
        }
    }

    // emit sorted top-K
    for (int r = t; r < TOPK; r += 1024) {
        unsigned long long key = keys[r];
        int idx = 32767 - (int)(key & 0x7FFFull);
        float score = __uint_as_float((unsigned)(key >> 15));
        int o = b * TOPK + r;
        g_topidx[o] = idx;
        g_topscore[o] = score;
        float4 bx = reinterpret_cast<const float4*>(boxes)[(size_t)b * NA + idx];
        reinterpret_cast<float4*>(g_topboxes)[o] = bx;
    }
}

// ---------------- K3: 64x64 suppression bit-tiles (upper triangle only) ----------------
__device__ __forceinline__ bool iou_sup(const float4& rb, float area1,
                                        const float4& c, float area2) {
    float lx = fmaxf(rb.x, c.x), ly = fmaxf(rb.y, c.y);
    float rx = fminf(rb.z, c.z), ry = fminf(rb.w, c.w);
    float w = fmaxf(rx - lx, 0.0f), h = fmaxf(ry - ly, 0.0f);
    float inter = w * h;
    if (inter > 0.0f) {
        float un = area1 + area2 - inter;
        return __fdiv_rn(inter, un) > NMS_T;   // IEEE div: matches XLA div.rn
    }
    return false;
}

__global__ void k_mask() {
    if (blockIdx.x < blockIdx.y) return;   // strictly-lower tiles stay zero (never written)
    const int b = blockIdx.z;
    const int rowblk = blockIdx.y, colblk = blockIdx.x;
    const int t = threadIdx.x;             // 64 threads
    __shared__ float4 colbox[64];
    __shared__ float colarea[64];

    const int col0 = colblk * 64;
    float4 cbl = reinterpret_cast<const float4*>(g_topboxes)[b * TOPK + col0 + t];
    colbox[t] = cbl;
    colarea[t] = (cbl.z - cbl.x) * (cbl.w - cbl.y);
    __syncthreads();

    const int row = rowblk * 64 + t;
    float4 rb = reinterpret_cast<const float4*>(g_topboxes)[b * TOPK + row];
    float area1 = (rb.z - rb.x) * (rb.w - rb.y);

    unsigned long long bits = 0ull;
    if (rowblk != colblk) {
#pragma unroll 4
        for (int j = 0; j < 64; ++j)
            if (iou_sup(rb, area1, colbox[j], colarea[j])) bits |= (1ull << j);
    } else {
#pragma unroll 4
        for (int j = 0; j < 64; ++j)
            if (col0 + j > row && iou_sup(rb, area1, colbox[j], colarea[j]))
                bits |= (1ull << j);
    }
    g_mask[((size_t)b * TOPK + row) * 32 + colblk] = bits;
}

// ---------------- K4: chunked greedy reduce (warp 0) + fused finalize ----------------
__device__ __forceinline__ void cp_async16(uint32_t saddr, const void* gptr) {
    asm volatile("cp.async.cg.shared.global [%0], [%1], 16;" :: "r"(saddr), "l"(gptr));
}

__device__ __forceinline__ void stage_chunk(const unsigned long long* __restrict__ Mc,
                                            unsigned long long* slot, int lane) {
    uint32_t s = (uint32_t)__cvta_generic_to_shared(slot) + lane * 16;
    const char* g = (const char*)Mc + lane * 16;
#pragma unroll
    for (int k = 0; k < 16; ++k)
        cp_async16(s + k * 512, g + k * 512);
    asm volatile("cp.async.commit_group;");
}

__global__ void __launch_bounds__(1024, 1) k_reduce_final(float* __restrict__ out) {
    __shared__ __align__(16) unsigned long long ring[4][1024];   // 32 KB
    __shared__ unsigned char keepsh[TOPK];
    const int b = blockIdx.x;
    const int t = threadIdx.x;

    if (t < 32) {
        const int lane = t;                    // lane owns column word lane (cols lane*64..+63)
        const unsigned long long* __restrict__ M = g_mask + (size_t)b * TOPK * 32;

        stage_chunk(M + 0 * 1024, ring[0], lane);
        stage_chunk(M + 1 * 1024, ring[1], lane);
        stage_chunk(M + 2 * 1024, ring[2], lane);

        unsigned long long keep0w = 0ull;
        const float* ts = g_topscore + b * TOPK;
#pragma unroll 8
        for (int q = 0; q < 64; ++q)
            if (ts[lane * 64 + q] > 0.0f) keep0w |= (1ull << q);

        unsigned long long removed = 0ull;

        for (int c = 0; c < 64; ++c) {
            asm volatile("cp.async.wait_group 2;");
            __syncwarp();

            const unsigned long long* rowp = ring[c & 3];
            const int owner = c >> 1;
            const int sh2 = (c & 1) * 32;

            unsigned d[32];
#pragma unroll
            for (int i = 0; i < 32; ++i)
                d[i] = (unsigned)(rowp[i * 32 + owner] >> sh2);

            unsigned long long av64 = __shfl_sync(FULLM, keep0w & ~removed, owner);
            unsigned alive = (unsigned)(av64 >> sh2);

#pragma unroll
            for (int i = 0; i < 32; ++i)
                alive &= ~(d[i] & (unsigned)((int)(alive << (31 - i)) >> 31));

#pragma unroll
            for (int i = 0; i < 32; ++i)
                if ((alive >> i) & 1u) removed |= rowp[i * 32 + lane];

            keepsh[c * 32 + lane] = (unsigned char)((alive >> lane) & 1u);

            stage_chunk(M + (size_t)((c + 3) & 63) * 1024, ring[(c + 3) & 3], lane);
        }
    }
    __syncthreads();

    // fused finalize: [boxes | scores | labels] as float32
#pragma unroll
    for (int r = t; r < TOPK; r += 1024) {
        int g = b * TOPK + r;
        bool k = keepsh[r] != 0;
        float m = k ? 1.0f : 0.0f;
        float4 bx = reinterpret_cast<const float4*>(g_topboxes)[g];
        reinterpret_cast<float4*>(out)[g] = make_float4(bx.x * m, bx.y * m, bx.z * m, bx.w * m);
        out[BATCH * TOPK * 4 + g] = k ? g_topscore[g] : 0.0f;
        int lab = g_labels[(size_t)b * NA + g_topidx[g]];
        out[BATCH * TOPK * 5 + g] = k ? (float)lab : 0.0f;
    }
}

// ---------------- launch ----------------
extern "C" void kernel_launch(void* const* d_in, const int* in_sizes, int n_in,
                              void* d_out, int out_size) {
    const float* boxes = (const float*)d_in[0];   // [16,25200,4]
    const float* obj   = (const float*)d_in[1];   // [16,25200]
    const float* cls   = (const float*)d_in[2];   // [16,25200,80]
    float* out = (float*)d_out;

    cudaFuncSetAttribute(k_topk, cudaFuncAttributeMaxDynamicSharedMemorySize, 65536);

    k_scores<<<(BATCH * NA) / 128, 128>>>(obj, cls);
    k_topk<<<BATCH, 1024, 65536>>>(boxes);
    dim3 g3(32, 32, BATCH);
    k_mask<<<g3, 64>>>();
    k_reduce_final<<<BATCH, 1024>>>(out);
}

// round 16
// speedup vs baseline: 1.1045x; 1.1045x over previous
#include <cuda_runtime.h>
#include <cstdint>

#define BATCH 16
#define NA    25200
#define NC    80
#define TOPK  2048
#define NMS_T 0.45f
#define CONF_T 0.25f
#define FULLM 0xffffffffu

// ---------------- scratch (__device__ globals; zero-initialized at load) ----------------
__device__ float              g_scores[BATCH * NA];          // conf-filtered max score
__device__ int                g_labels[BATCH * NA];          // argmax class
__device__ float              g_topboxes[BATCH * TOPK * 4];  // gathered boxes (xyxy)
__device__ float              g_topscore[BATCH * TOPK];
__device__ int                g_topidx[BATCH * TOPK];
__device__ __align__(16) unsigned long long g_mask[(size_t)BATCH * TOPK * 32]; // 8MB bit-matrix

// ---------------- K1: score/argmax, smem-staged coalesced loads ----------------
__global__ void __launch_bounds__(128) k_scores(const float* __restrict__ obj,
                                                const float* __restrict__ cls) {
    __shared__ float sh[128 * 81];                 // 81-stride: conflict-free reduce
    const int t = threadIdx.x;
    const int a0 = blockIdx.x * 128;               // first flattened anchor of block
    const float4* __restrict__ src = reinterpret_cast<const float4*>(cls) + (size_t)a0 * 20;

#pragma unroll
    for (int k = 0; k < 20; ++k) {                 // perfectly coalesced gmem loads
        int fi = k * 128 + t;
        float4 v = src[fi];
        int a = fi / 20, c = (fi % 20) * 4;
        float* row = sh + a * 81 + c;
        row[0] = v.x; row[1] = v.y; row[2] = v.z; row[3] = v.w;
    }
    __syncthreads();

    const int g = a0 + t;
    const float o = obj[g];
    const float* row = sh + t * 81;
    float best = -1.0f; int bi = 0;
#pragma unroll
    for (int c = 0; c < NC; ++c) {                 // strict > : first-index argmax
        float p = o * row[c];
        if (p > best) { best = p; bi = c; }
    }
    g_scores[g] = (best > CONF_T) ? best : 0.0f;
    g_labels[g] = bi;
}

// ---------------- K2: per-image exact top-2048 (sorted desc, tie -> low idx) ----------------
// composite key: (float_bits(score) << 15) | (32767 - idx)   -- 48 bits, all distinct
// 4-pass 12-bit radix select with warp-parallel 3-level digit search. (R14 proven version)
__global__ void k_topk(const float* __restrict__ boxes) {
    const int b = blockIdx.x;
    const int t = threadIdx.x;                 // 1024 threads
    const float* __restrict__ sc = g_scores + (size_t)b * NA;

    __shared__ unsigned int hist[4096];
    __shared__ unsigned long long keys[TOPK];
    __shared__ unsigned long long sh_prefix;
    __shared__ int sh_rem;
    __shared__ unsigned int sh_cnt;

    if (t == 0) { sh_prefix = 0ull; sh_rem = TOPK; sh_cnt = 0u; }
    for (int i = t; i < TOPK; i += 1024) keys[i] = 0ull;
    __syncthreads();

    for (int shift = 36; shift >= 0; shift -= 12) {
        for (int i = t; i < 4096; i += 1024) hist[i] = 0u;
        __syncthreads();
        unsigned long long prefix = sh_prefix;
        for (int n = t; n < NA; n += 1024) {
            unsigned long long key =
                ((unsigned long long)__float_as_uint(sc[n]) << 15) |
                (unsigned long long)(32767 - n);
            if ((key >> (shift + 12)) == prefix)
                atomicAdd(&hist[(unsigned)(key >> shift) & 4095u], 1u);
        }
        __syncthreads();
        if (t < 32) {                              // warp 0: parallel digit search
            const int lane = t;
            unsigned rem = (unsigned)sh_rem;
            // --- level 1: lane covers 128 bins ---
            unsigned a0 = 0, a1 = 0, a2 = 0, a3 = 0;
            int base1 = lane * 128;
            for (int i = 0; i < 128; i += 4) {
                a0 += hist[base1 + i + 0]; a1 += hist[base1 + i + 1];
                a2 += hist[base1 + i + 2]; a3 += hist[base1 + i + 3];
            }
            unsigned c1 = a0 + a1 + a2 + a3;
            unsigned v = c1;                       // inclusive suffix sum over lanes
            for (int o = 1; o < 32; o <<= 1) {
                unsigned u = __shfl_down_sync(FULLM, v, o);
                if (lane + o < 32) v += u;
            }
            unsigned sufex = v - c1;
            unsigned bal = __ballot_sync(FULLM, (sufex < rem) && (rem <= v));
            int L1 = __ffs(bal) - 1;
            rem -= __shfl_sync(FULLM, sufex, L1);
            // --- level 2: 4 bins per lane inside region L1 ---
            int base2 = L1 * 128 + lane * 4;
            unsigned c2 = hist[base2] + hist[base2 + 1] + hist[base2 + 2] + hist[base2 + 3];
            v = c2;
            for (int o = 1; o < 32; o <<= 1) {
                unsigned u = __shfl_down_sync(FULLM, v, o);
                if (lane + o < 32) v += u;
            }
            sufex = v - c2;
            bal = __ballot_sync(FULLM, (sufex < rem) && (rem <= v));
            int L2 = __ffs(bal) - 1;
            rem -= __shfl_sync(FULLM, sufex, L2);
            // --- level 3: serial over 4 bins (high digit first) ---
            if (lane == L2) {
                int b3 = L1 * 128 + L2 * 4;
                unsigned cum = 0; int d = 3;
                for (d = 3; d >= 0; --d) {
                    unsigned h = hist[b3 + d];
                    if (cum + h >= rem) break;
                    cum += h;
                }
                sh_prefix = (prefix << 12) | (unsigned long long)(unsigned)(b3 + d);
                sh_rem = (int)(rem - cum);
            }
        }
        __syncthreads();
    }
    const unsigned long long T = sh_prefix;    // exact K-th largest key

    // collect all keys >= T (exactly TOPK, keys are distinct)
    for (int n = t; n < NA; n += 1024) {
        unsigned long long key =
            ((unsigned long long)__float_as_uint(sc[n]) << 15) |
            (unsigned long long)(32767 - n);
        if (key >= T) {
            unsigned p = atomicAdd(&sh_cnt, 1u);
            if (p < TOPK) keys[p] = key;
        }
    }
    __syncthreads();

    // bitonic sort descending (2048 elems, 1024 threads)
    for (int kk = 2; kk <= TOPK; kk <<= 1) {
        for (int j = kk >> 1; j > 0; j >>= 1) {
            for (int i = t; i < TOPK; i += 1024) {
                int l = i ^ j;
                if (l > i) {
                    bool dir = ((i & kk) == 0);  // true -> descending
                    unsigned long long a = keys[i], c = keys[l];
                    if ((a < c) == dir) { keys[i] = c; keys[l] = a; }
                }
            }
            __syncthreads();
        }
    }

    // emit sorted top-K: score, idx, gathered box
    for (int r = t; r < TOPK; r += 1024) {
        unsigned long long key = keys[r];
        int idx = 32767 - (int)(key & 0x7FFFull);
        float score = __uint_as_float((unsigned)(key >> 15));
        int o = b * TOPK + r;
        g_topidx[o] = idx;
        g_topscore[o] = score;
        float4 bx = reinterpret_cast<const float4*>(boxes)[(size_t)b * NA + idx];
        reinterpret_cast<float4*>(g_topboxes)[o] = bx;
    }
}

// ---------------- K3: 64x64 suppression bit-tiles (upper triangle only) ----------------
__device__ __forceinline__ bool iou_sup(const float4& rb, float area1,
                                        const float4& c, float area2) {
    float lx = fmaxf(rb.x, c.x), ly = fmaxf(rb.y, c.y);
    float rx = fminf(rb.z, c.z), ry = fminf(rb.w, c.w);
    float w = fmaxf(rx - lx, 0.0f), h = fmaxf(ry - ly, 0.0f);
    float inter = w * h;
    if (inter > 0.0f) {
        float un = area1 + area2 - inter;
        return __fdiv_rn(inter, un) > NMS_T;   // IEEE div: matches XLA div.rn
    }
    return false;
}

__global__ void k_mask() {
    if (blockIdx.x < blockIdx.y) return;   // strictly-lower tiles stay zero (never written)
    const int b = blockIdx.z;
    const int rowblk = blockIdx.y, colblk = blockIdx.x;
    const int t = threadIdx.x;             // 64 threads
    __shared__ float4 colbox[64];
    __shared__ float colarea[64];

    const int col0 = colblk * 64;
    float4 cbl = reinterpret_cast<const float4*>(g_topboxes)[b * TOPK + col0 + t];
    colbox[t] = cbl;
    colarea[t] = (cbl.z - cbl.x) * (cbl.w - cbl.y);
    __syncthreads();

    const int row = rowblk * 64 + t;
    float4 rb = reinterpret_cast<const float4*>(g_topboxes)[b * TOPK + row];
    float area1 = (rb.z - rb.x) * (rb.w - rb.y);

    unsigned long long bits = 0ull;
    if (rowblk != colblk) {
#pragma unroll 4
        for (int j = 0; j < 64; ++j)
            if (iou_sup(rb, area1, colbox[j], colarea[j])) bits |= (1ull << j);
    } else {
#pragma unroll 4
        for (int j = 0; j < 64; ++j)
            if (col0 + j > row && iou_sup(rb, area1, colbox[j], colarea[j]))
                bits |= (1ull << j);
    }
    g_mask[((size_t)b * TOPK + row) * 32 + colblk] = bits;
}

// ---------------- K4: chunked greedy reduce (warp 0) + fused finalize ----------------
__device__ __forceinline__ void cp_async16(uint32_t saddr, const void* gptr) {
    asm volatile("cp.async.cg.shared.global [%0], [%1], 16;" :: "r"(saddr), "l"(gptr));
}

__device__ __forceinline__ void stage_chunk(const unsigned long long* __restrict__ Mc,
                                            unsigned long long* slot, int lane) {
    uint32_t s = (uint32_t)__cvta_generic_to_shared(slot) + lane * 16;
    const char* g = (const char*)Mc + lane * 16;
#pragma unroll
    for (int k = 0; k < 16; ++k)
        cp_async16(s + k * 512, g + k * 512);
    asm volatile("cp.async.commit_group;");
}

__global__ void __launch_bounds__(1024, 1) k_reduce_final(float* __restrict__ out) {
    __shared__ __align__(16) unsigned long long ring[4][1024];   // 32 KB
    __shared__ unsigned char keepsh[TOPK];
    const int b = blockIdx.x;
    const int t = threadIdx.x;

    if (t < 32) {
        const int lane = t;                    // lane owns column word lane (cols lane*64..+63)
        const unsigned long long* __restrict__ M = g_mask + (size_t)b * TOPK * 32;

        stage_chunk(M + 0 * 1024, ring[0], lane);
        stage_chunk(M + 1 * 1024, ring[1], lane);
        stage_chunk(M + 2 * 1024, ring[2], lane);

        unsigned long long keep0w = 0ull;
        const float* ts = g_topscore + b * TOPK;
#pragma unroll 8
        for (int q = 0; q < 64; ++q)
            if (ts[lane * 64 + q] > 0.0f) keep0w |= (1ull << q);

        unsigned long long removed = 0ull;

        for (int c = 0; c < 64; ++c) {
            asm volatile("cp.async.wait_group 2;");
            __syncwarp();

            const unsigned long long* rowp = ring[c & 3];
            const int owner = c >> 1;
            const int sh2 = (c & 1) * 32;

            unsigned d[32];
#pragma unroll
            for (int i = 0; i < 32; ++i)
                d[i] = (unsigned)(rowp[i * 32 + owner] >> sh2);

            unsigned long long av64 = __shfl_sync(FULLM, keep0w & ~removed, owner);
            unsigned alive = (unsigned)(av64 >> sh2);

#pragma unroll
            for (int i = 0; i < 32; ++i)
                alive &= ~(d[i] & (unsigned)((int)(alive << (31 - i)) >> 31));

#pragma unroll
            for (int i = 0; i < 32; ++i)
                if ((alive >> i) & 1u) removed |= rowp[i * 32 + lane];

            keepsh[c * 32 + lane] = (unsigned char)((alive >> lane) & 1u);

            stage_chunk(M + (size_t)((c + 3) & 63) * 1024, ring[(c + 3) & 3], lane);
        }
    }
    __syncthreads();

    // fused finalize: [boxes | scores | labels] as float32
#pragma unroll
    for (int r = t; r < TOPK; r += 1024) {
        int g = b * TOPK + r;
        bool k = keepsh[r] != 0;
        float m = k ? 1.0f : 0.0f;
        float4 bx = reinterpret_cast<const float4*>(g_topboxes)[g];
        reinterpret_cast<float4*>(out)[g] = make_float4(bx.x * m, bx.y * m, bx.z * m, bx.w * m);
        out[BATCH * TOPK * 4 + g] = k ? g_topscore[g] : 0.0f;
        int lab = g_labels[(size_t)b * NA + g_topidx[g]];
        out[BATCH * TOPK * 5 + g] = k ? (float)lab : 0.0f;
    }
}

// ---------------- launch ----------------
extern "C" void kernel_launch(void* const* d_in, const int* in_sizes, int n_in,
                              void* d_out, int out_size) {
    const float* boxes = (const float*)d_in[0];   // [16,25200,4]
    const float* obj   = (const float*)d_in[1];   // [16,25200]
    const float* cls   = (const float*)d_in[2];   // [16,25200,80]
    float* out = (float*)d_out;

    k_scores<<<(BATCH * NA) / 128, 128>>>(obj, cls);
    k_topk<<<BATCH, 1024>>>(boxes);
    dim3 g3(32, 32, BATCH);
    k_mask<<<g3, 64>>>();
    k_reduce_final<<<BATCH, 1024>>>(out);
}